// round 1
// baseline (speedup 1.0000x reference)
#include <cuda_runtime.h>
#include <cuda_bf16.h>

#define NMAX 100000
#define EMAX 2000000
#define D    64

// Scratch (device globals: no allocation allowed in kernel_launch)
__device__ float g_agg[NMAX * D];     // neighbor-sum accumulator
__device__ float g_h[NMAX * D];       // layer-0 output
__device__ float g_invdeg[NMAX];
__device__ int   g_deg[NMAX];

// ---------------------------------------------------------------------------
// Zero agg (float4) and deg
// ---------------------------------------------------------------------------
__global__ void zero_kernel(int n) {
    int i = blockIdx.x * blockDim.x + threadIdx.x;
    int nq = n * (D / 4);                 // float4 count for agg
    if (i < nq) reinterpret_cast<float4*>(g_agg)[i] = make_float4(0.f, 0.f, 0.f, 0.f);
    if (i < n)  g_deg[i] = 0;
}

// ---------------------------------------------------------------------------
// Degree histogram: 4 edges per thread via int4
// ---------------------------------------------------------------------------
__global__ void deg_kernel(const int* __restrict__ dst, int e) {
    int i = blockIdx.x * blockDim.x + threadIdx.x;
    int base = i * 4;
    if (base + 3 < e) {
        int4 d = reinterpret_cast<const int4*>(dst)[i];
        atomicAdd(&g_deg[d.x], 1);
        atomicAdd(&g_deg[d.y], 1);
        atomicAdd(&g_deg[d.z], 1);
        atomicAdd(&g_deg[d.w], 1);
    } else {
        for (int k = base; k < e; k++) atomicAdd(&g_deg[dst[k]], 1);
    }
}

__global__ void invdeg_kernel(int n) {
    int i = blockIdx.x * blockDim.x + threadIdx.x;
    if (i < n) g_invdeg[i] = 1.0f / fmaxf((float)g_deg[i], 1.0f);
}

// ---------------------------------------------------------------------------
// Edge scatter: 16 threads per edge, each owns one float4 of the 64-f row.
// Gather h[src] (L2-resident) and vector-atomic into g_agg[dst].
// ---------------------------------------------------------------------------
__global__ void scatter_kernel(const float4* __restrict__ h,
                               const int* __restrict__ src,
                               const int* __restrict__ dst, int e) {
    long long t = (long long)blockIdx.x * blockDim.x + threadIdx.x;
    int edge = (int)(t >> 4);
    int lane = (int)(t & 15);
    if (edge >= e) return;
    int s = __ldg(&src[edge]);
    int d = __ldg(&dst[edge]);
    float4 v = __ldg(&h[(long long)s * (D / 4) + lane]);
    atomicAdd(reinterpret_cast<float4*>(g_agg) + (long long)d * (D / 4) + lane, v);
}

// ---------------------------------------------------------------------------
// Fused linear: out[i] = act( concat(hin[i], agg[i]*invdeg[i]) @ W + b )
// 256 threads/block = 4 nodes x 64 columns. W cached in shared (32 KB).
// Layer 0 additionally re-zeroes agg in place (ready for layer-1 scatter).
// ---------------------------------------------------------------------------
template <bool RELU, bool ZERO_AGG>
__global__ void linear_kernel(const float* __restrict__ hin,
                              const float* __restrict__ W,
                              const float* __restrict__ b,
                              float* __restrict__ hout, int n) {
    __shared__ float Ws[2 * D * D];     // 128 x 64
    __shared__ float ins[4][2 * D];     // concat rows for 4 nodes

    int tid = threadIdx.x;
    // Cooperative W load (2048 float4 / 256 threads = 8 each)
    for (int i = tid; i < (2 * D * D) / 4; i += 256)
        reinterpret_cast<float4*>(Ws)[i] = reinterpret_cast<const float4*>(W)[i];

    int g = tid >> 6;       // node slot 0..3
    int j = tid & 63;       // output column
    int node = blockIdx.x * 4 + g;

    if (node < n) {
        float id = g_invdeg[node];
        ins[g][j]     = hin[(long long)node * D + j];
        float a = g_agg[(long long)node * D + j];
        ins[g][D + j] = a * id;
        if (ZERO_AGG) g_agg[(long long)node * D + j] = 0.0f;
    }
    __syncthreads();
    if (node >= n) return;

    float acc = __ldg(&b[j]);
#pragma unroll
    for (int k = 0; k < 2 * D; k++)
        acc = fmaf(ins[g][k], Ws[k * D + j], acc);

    if (RELU) acc = fmaxf(acc, 0.0f);
    hout[(long long)node * D + j] = acc;
}

// ---------------------------------------------------------------------------
extern "C" void kernel_launch(void* const* d_in, const int* in_sizes, int n_in,
                              void* d_out, int out_size) {
    const float* x  = (const float*)d_in[0];          // [N, 64]
    const int*   ei = (const int*)d_in[1];            // [2, E]
    const float* W0 = (const float*)d_in[2];          // [128, 64]
    const float* b0 = (const float*)d_in[3];          // [64]
    const float* W1 = (const float*)d_in[4];          // [128, 64]
    const float* b1 = (const float*)d_in[5];          // [64]
    float*       out = (float*)d_out;                 // [N, 64]

    int n = in_sizes[0] / D;
    int e = in_sizes[1] / 2;
    const int* src = ei;
    const int* dst = ei + e;

    float* hbuf;
    float* dummy;
    // Device-global pointers are used directly inside kernels; only g_h needs a
    // host-side handle for passing as hin to layer 1. Use symbol address.
    cudaGetSymbolAddress((void**)&hbuf, g_h);
    (void)dummy;

    // 1) zero agg + deg
    {
        int total = n * (D / 4);        // covers both agg quads and deg range
        zero_kernel<<<(total + 255) / 256, 256>>>(n);
    }
    // 2) degree
    deg_kernel<<<((e + 3) / 4 + 255) / 256, 256>>>(dst, e);
    // 3) inv degree
    invdeg_kernel<<<(n + 255) / 256, 256>>>(n);

    // 4) layer 0 scatter: x -> agg
    {
        long long threads = (long long)e * 16;
        int grid = (int)((threads + 255) / 256);
        scatter_kernel<<<grid, 256>>>((const float4*)x, src, dst, e);
    }
    // 5) layer 0 linear (+relu, zero agg after read)
    linear_kernel<true, true><<<(n + 3) / 4, 256>>>(x, W0, b0, hbuf, n);

    // 6) layer 1 scatter: h -> agg
    {
        long long threads = (long long)e * 16;
        int grid = (int)((threads + 255) / 256);
        scatter_kernel<<<grid, 256>>>((const float4*)hbuf, src, dst, e);
    }
    // 7) layer 1 linear (no relu) -> d_out
    linear_kernel<false, false><<<(n + 3) / 4, 256>>>(hbuf, W1, b1, out, n);
}

// round 3
// speedup vs baseline: 1.1686x; 1.1686x over previous
#include <cuda_runtime.h>
#include <cuda_bf16.h>

#define NMAX 100000
#define EMAX 2000000
#define D    64

// Scratch (device globals — no allocation allowed)
__device__ int   g_deg[NMAX];
__device__ int   g_off[NMAX + 1];
__device__ int   g_cursor[NMAX];
__device__ float g_invdeg[NMAX];
__device__ int   g_csr[EMAX];        // src node per edge, grouped by dst
__device__ float g_agg[NMAX * D];
__device__ float g_h[NMAX * D];

// ---------------------------------------------------------------------------
__global__ void zero_deg(int n) {
    int i = blockIdx.x * blockDim.x + threadIdx.x;
    if (i < n) g_deg[i] = 0;
}

// Degree histogram: 4 edges per thread via int4
__global__ void deg_kernel(const int* __restrict__ dst, int e) {
    int i = blockIdx.x * blockDim.x + threadIdx.x;
    int base = i * 4;
    if (base + 3 < e) {
        int4 d = reinterpret_cast<const int4*>(dst)[i];
        atomicAdd(&g_deg[d.x], 1);
        atomicAdd(&g_deg[d.y], 1);
        atomicAdd(&g_deg[d.z], 1);
        atomicAdd(&g_deg[d.w], 1);
    } else {
        for (int k = base; k < e; k++) atomicAdd(&g_deg[dst[k]], 1);
    }
}

// Single-block exclusive scan of deg -> off/cursor, plus invdeg. 1024 threads.
__global__ void scan_kernel(int n, int e) {
    __shared__ int sbuf[2][1024];
    int t = threadIdx.x;
    int npt = (n + 1023) >> 10;
    int beg = t * npt;
    int end = min(beg + npt, n);
    int local = 0;
    for (int i = beg; i < end; i++) local += g_deg[i];
    sbuf[0][t] = local;
    __syncthreads();
    int cur = 0;
    for (int s = 1; s < 1024; s <<= 1) {
        int v = sbuf[cur][t];
        if (t >= s) v += sbuf[cur][t - s];
        sbuf[cur ^ 1][t] = v;
        cur ^= 1;
        __syncthreads();
    }
    int run = sbuf[cur][t] - local;   // exclusive prefix for this chunk
    for (int i = beg; i < end; i++) {
        int d = g_deg[i];
        g_off[i] = run;
        g_cursor[i] = run;
        g_invdeg[i] = 1.0f / fmaxf((float)d, 1.0f);
        run += d;
    }
    if (t == 0) g_off[n] = e;
}

// CSR fill: per-edge atomic bump of per-node cursor
__global__ void fill_kernel(const int* __restrict__ src,
                            const int* __restrict__ dst, int e) {
    int i = blockIdx.x * blockDim.x + threadIdx.x;
    if (i < e) {
        int p = atomicAdd(&g_cursor[dst[i]], 1);
        g_csr[p] = src[i];
    }
}

// ---------------------------------------------------------------------------
// Aggregation (gather, no atomics): one warp per node. Lanes cooperatively
// load 32 neighbor indices, broadcast via shfl, accumulate float2 per lane.
// ---------------------------------------------------------------------------
__global__ void agg_kernel(const float2* __restrict__ h2, int n) {
    int node = blockIdx.x * 8 + (threadIdx.x >> 5);
    int lane = threadIdx.x & 31;
    if (node >= n) return;
    int beg = g_off[node];
    int end = g_off[node + 1];
    float2 acc = make_float2(0.f, 0.f);
    for (int base = beg; base < end; base += 32) {
        int idx = base + lane;
        int s = (idx < end) ? __ldg(&g_csr[idx]) : 0;
        int cnt = min(32, end - base);
        for (int k = 0; k < cnt; k++) {
            int sk = __shfl_sync(0xffffffffu, s, k);
            float2 v = __ldg(&h2[(long long)sk * 32 + lane]);
            acc.x += v.x;
            acc.y += v.y;
        }
    }
    float id = g_invdeg[node];
    reinterpret_cast<float2*>(g_agg)[(long long)node * 32 + lane] =
        make_float2(acc.x * id, acc.y * id);
}

// ---------------------------------------------------------------------------
// Fused linear: out = act( concat(hin, agg) @ W + b )
// Persistent blocks: W loaded once per block. 256 threads = 16 nodes x 16
// float4 column groups. 4 FFMA per (LDS.128 + broadcast LDS).
// ---------------------------------------------------------------------------
template <bool RELU>
__global__ __launch_bounds__(256) void linear_kernel(
    const float4* __restrict__ hin4, const float4* __restrict__ agg4,
    const float4* __restrict__ W4,   // [128][16] float4
    const float* __restrict__ b, float4* __restrict__ out4, int n)
{
    __shared__ float4 Ws[128 * 16];  // 32 KB
    __shared__ float  ins[16][128];  // 8 KB: 16 concat rows

    int tid = threadIdx.x;
    for (int i = tid; i < 2048; i += 256) Ws[i] = W4[i];

    int slot = tid >> 4;
    int j4   = tid & 15;
    float4 bias = reinterpret_cast<const float4*>(b)[j4];

    int ntiles = (n + 15) >> 4;
    for (int tile = blockIdx.x; tile < ntiles; tile += gridDim.x) {
        __syncthreads();
        // stage 16 concat rows: 512 float4, 2 per thread
        #pragma unroll
        for (int r = 0; r < 2; r++) {
            int idx = tid + 256 * r;        // 0..511
            int sl = idx >> 5;
            int q  = idx & 31;
            int node = tile * 16 + sl;
            float4 v = make_float4(0.f, 0.f, 0.f, 0.f);
            if (node < n)
                v = (q < 16) ? __ldg(&hin4[(long long)node * 16 + q])
                             : __ldg(&agg4[(long long)node * 16 + (q - 16)]);
            *reinterpret_cast<float4*>(&ins[sl][q * 4]) = v;
        }
        __syncthreads();

        int node = tile * 16 + slot;
        if (node < n) {
            float4 acc = bias;
            #pragma unroll
            for (int k = 0; k < 128; k++) {
                float  f = ins[slot][k];
                float4 w = Ws[k * 16 + j4];
                acc.x = fmaf(f, w.x, acc.x);
                acc.y = fmaf(f, w.y, acc.y);
                acc.z = fmaf(f, w.z, acc.z);
                acc.w = fmaf(f, w.w, acc.w);
            }
            if (RELU) {
                acc.x = fmaxf(acc.x, 0.f);
                acc.y = fmaxf(acc.y, 0.f);
                acc.z = fmaxf(acc.z, 0.f);
                acc.w = fmaxf(acc.w, 0.f);
            }
            out4[(long long)node * 16 + j4] = acc;
        }
    }
}

// ---------------------------------------------------------------------------
extern "C" void kernel_launch(void* const* d_in, const int* in_sizes, int n_in,
                              void* d_out, int out_size) {
    const float* x  = (const float*)d_in[0];          // [N, 64]
    const int*   ei = (const int*)d_in[1];            // [2, E]
    const float* W0 = (const float*)d_in[2];          // [128, 64]
    const float* b0 = (const float*)d_in[3];          // [64]
    const float* W1 = (const float*)d_in[4];          // [128, 64]
    const float* b1 = (const float*)d_in[5];          // [64]
    float*       out = (float*)d_out;                 // [N, 64]

    int n = in_sizes[0] / D;
    int e = in_sizes[1] / 2;
    const int* src = ei;
    const int* dst = ei + e;

    float* hbuf;
    float* aggbuf;
    cudaGetSymbolAddress((void**)&hbuf, g_h);
    cudaGetSymbolAddress((void**)&aggbuf, g_agg);

    // --- CSR build (reused by both layers) ---
    zero_deg<<<(n + 255) / 256, 256>>>(n);
    deg_kernel<<<((e + 3) / 4 + 255) / 256, 256>>>(dst, e);
    scan_kernel<<<1, 1024>>>(n, e);
    fill_kernel<<<(e + 255) / 256, 256>>>(src, dst, e);

    const int LIN_GRID = 740;   // ~5 blocks/SM by smem (40KB)

    // --- Layer 0 ---
    agg_kernel<<<(n + 7) / 8, 256>>>((const float2*)x, n);
    linear_kernel<true><<<LIN_GRID, 256>>>(
        (const float4*)x, (const float4*)aggbuf,
        (const float4*)W0, b0, (float4*)hbuf, n);

    // --- Layer 1 ---
    agg_kernel<<<(n + 7) / 8, 256>>>((const float2*)hbuf, n);
    linear_kernel<false><<<LIN_GRID, 256>>>(
        (const float4*)hbuf, (const float4*)aggbuf,
        (const float4*)W1, b1, (float4*)out, n);
}

// round 5
// speedup vs baseline: 3.1657x; 2.7089x over previous
#include <cuda_runtime.h>
#include <cuda_bf16.h>
#include <cstdint>

#define NMAX 100000
#define EMAX 2000000
#define D    64

// ---------------------------------------------------------------------------
// Scratch (device globals — no allocation allowed)
// ---------------------------------------------------------------------------
__device__ int   g_deg[NMAX];
__device__ int   g_off[NMAX + 1];
__device__ int   g_cursor[NMAX];
__device__ float g_invdeg[NMAX];
__device__ int   g_csr[EMAX];
__device__ float g_agg[NMAX * D];
__device__ float g_h[NMAX * D];
__device__ int   g_bsum[64];
__device__ int   g_boff[64];

__device__ __forceinline__ uint32_t cvt_tf32(float f) {
    uint32_t r;
    asm("cvt.rna.tf32.f32 %0, %1;" : "=r"(r) : "f"(f));
    return r;
}

// ---------------------------------------------------------------------------
// CSR build
// ---------------------------------------------------------------------------
__global__ void zero_deg(int n) {
    int i = blockIdx.x * blockDim.x + threadIdx.x;
    if (i < n) g_deg[i] = 0;
}

__global__ void deg_kernel(const int* __restrict__ dst, int e) {
    int i = blockIdx.x * blockDim.x + threadIdx.x;
    int base = i * 8;
    if (base + 7 < e) {
        int d0 = __ldg(&dst[base + 0]), d1 = __ldg(&dst[base + 1]);
        int d2 = __ldg(&dst[base + 2]), d3 = __ldg(&dst[base + 3]);
        int d4 = __ldg(&dst[base + 4]), d5 = __ldg(&dst[base + 5]);
        int d6 = __ldg(&dst[base + 6]), d7 = __ldg(&dst[base + 7]);
        atomicAdd(&g_deg[d0], 1); atomicAdd(&g_deg[d1], 1);
        atomicAdd(&g_deg[d2], 1); atomicAdd(&g_deg[d3], 1);
        atomicAdd(&g_deg[d4], 1); atomicAdd(&g_deg[d5], 1);
        atomicAdd(&g_deg[d6], 1); atomicAdd(&g_deg[d7], 1);
    } else {
        for (int k = base; k < e; k++) atomicAdd(&g_deg[dst[k]], 1);
    }
}

// 3-phase parallel scan (2048 nodes per block)
__global__ void scan_sum(int n) {
    __shared__ int sh[256];
    int b = blockIdx.x, t = threadIdx.x;
    int base = b * 2048 + t * 8;
    int s = 0;
    for (int i = 0; i < 8; i++) { int nd = base + i; if (nd < n) s += g_deg[nd]; }
    sh[t] = s; __syncthreads();
    for (int off = 128; off > 0; off >>= 1) {
        if (t < off) sh[t] += sh[t + off];
        __syncthreads();
    }
    if (t == 0) g_bsum[b] = sh[0];
}

__global__ void scan_blocks(int nb, int n, int e) {
    __shared__ int sh[64];
    int t = threadIdx.x;  // 64 threads
    int v = (t < nb) ? g_bsum[t] : 0;
    sh[t] = v; __syncthreads();
    for (int off = 1; off < 64; off <<= 1) {
        int x = sh[t];
        if (t >= off) x += sh[t - off];
        __syncthreads(); sh[t] = x; __syncthreads();
    }
    if (t < nb) g_boff[t] = sh[t] - v;
    if (t == 0) g_off[n] = e;
}

__global__ void scan_apply(int n) {
    __shared__ int sh[256];
    int b = blockIdx.x, t = threadIdx.x;
    int base = b * 2048 + t * 8;
    int d[8]; int s = 0;
    for (int i = 0; i < 8; i++) {
        int nd = base + i;
        d[i] = (nd < n) ? g_deg[nd] : 0;
        s += d[i];
    }
    sh[t] = s; __syncthreads();
    for (int off = 1; off < 256; off <<= 1) {
        int x = sh[t];
        if (t >= off) x += sh[t - off];
        __syncthreads(); sh[t] = x; __syncthreads();
    }
    int run = g_boff[b] + sh[t] - s;
    for (int i = 0; i < 8; i++) {
        int nd = base + i;
        if (nd < n) {
            g_off[nd] = run;
            g_cursor[nd] = run;
            g_invdeg[nd] = 1.0f / fmaxf((float)d[i], 1.0f);
            run += d[i];
        }
    }
}

__global__ void fill_kernel(const int* __restrict__ src,
                            const int* __restrict__ dst, int e) {
    int i = blockIdx.x * blockDim.x + threadIdx.x;
    int base = i * 4;
    if (base + 3 < e) {
        int d0 = __ldg(&dst[base]), d1 = __ldg(&dst[base + 1]);
        int d2 = __ldg(&dst[base + 2]), d3 = __ldg(&dst[base + 3]);
        int s0 = __ldg(&src[base]), s1 = __ldg(&src[base + 1]);
        int s2 = __ldg(&src[base + 2]), s3 = __ldg(&src[base + 3]);
        int p0 = atomicAdd(&g_cursor[d0], 1);
        int p1 = atomicAdd(&g_cursor[d1], 1);
        int p2 = atomicAdd(&g_cursor[d2], 1);
        int p3 = atomicAdd(&g_cursor[d3], 1);
        g_csr[p0] = s0; g_csr[p1] = s1; g_csr[p2] = s2; g_csr[p3] = s3;
    } else {
        for (int k = base; k < e; k++) {
            int p = atomicAdd(&g_cursor[dst[k]], 1);
            g_csr[p] = src[k];
        }
    }
}

// ---------------------------------------------------------------------------
// Aggregation: warp per node, 4x unrolled neighbor loop for MLP
// ---------------------------------------------------------------------------
__global__ void agg_kernel(const float2* __restrict__ h2, int n) {
    int node = blockIdx.x * 8 + (threadIdx.x >> 5);
    int lane = threadIdx.x & 31;
    if (node >= n) return;
    int beg = g_off[node];
    int end = g_off[node + 1];
    float2 acc = make_float2(0.f, 0.f);
    for (int base = beg; base < end; base += 32) {
        int idx = base + lane;
        int s = (idx < end) ? __ldg(&g_csr[idx]) : 0;
        int cnt = min(32, end - base);
        int k = 0;
        for (; k + 4 <= cnt; k += 4) {
            int s0 = __shfl_sync(0xffffffffu, s, k);
            int s1 = __shfl_sync(0xffffffffu, s, k + 1);
            int s2 = __shfl_sync(0xffffffffu, s, k + 2);
            int s3 = __shfl_sync(0xffffffffu, s, k + 3);
            float2 v0 = __ldg(&h2[(size_t)s0 * 32 + lane]);
            float2 v1 = __ldg(&h2[(size_t)s1 * 32 + lane]);
            float2 v2 = __ldg(&h2[(size_t)s2 * 32 + lane]);
            float2 v3 = __ldg(&h2[(size_t)s3 * 32 + lane]);
            acc.x += (v0.x + v1.x) + (v2.x + v3.x);
            acc.y += (v0.y + v1.y) + (v2.y + v3.y);
        }
        for (; k < cnt; k++) {
            int sk = __shfl_sync(0xffffffffu, s, k);
            float2 v = __ldg(&h2[(size_t)sk * 32 + lane]);
            acc.x += v.x; acc.y += v.y;
        }
    }
    float id = g_invdeg[node];
    reinterpret_cast<float2*>(g_agg)[(size_t)node * 32 + lane] =
        make_float2(acc.x * id, acc.y * id);
}

// ---------------------------------------------------------------------------
// tf32 mma.sync linear: out = act( concat(hin, agg) @ W + b )
// Persistent blocks. Tile = 64 nodes x 64 cols, K = 128 (16 k8 steps).
// 8 warps = 2 row-groups x 4 col-groups; each warp: 2 m16 x 2 n8 tiles.
// W register-resident per warp (preloaded once). K-slot remap: hardware slot
// (tg, hi) <- logical k = 2*tg + hi for BOTH A and B, so A fragment pairs
// {a0,a2}/{a1,a3} are contiguous LDS.64 loads from row-major smem.
// ---------------------------------------------------------------------------
#define A_STRIDE 132   // floats; 528B per row: 16B-aligned, banks rotate 4/row

__device__ __forceinline__ void mma_tf32(float& c0, float& c1, float& c2, float& c3,
                                         uint32_t a0, uint32_t a1, uint32_t a2, uint32_t a3,
                                         uint32_t b0, uint32_t b1) {
    asm volatile("mma.sync.aligned.m16n8k8.row.col.f32.tf32.tf32.f32 "
                 "{%0,%1,%2,%3}, {%4,%5,%6,%7}, {%8,%9}, {%0,%1,%2,%3};"
                 : "+f"(c0), "+f"(c1), "+f"(c2), "+f"(c3)
                 : "r"(a0), "r"(a1), "r"(a2), "r"(a3), "r"(b0), "r"(b1));
}

template <bool RELU>
__global__ __launch_bounds__(256) void linear_mma(
    const float4* __restrict__ hin4, const float4* __restrict__ agg4,
    const float* __restrict__ W, const float* __restrict__ bias,
    float* __restrict__ out, int n)
{
    __shared__ float As[64 * A_STRIDE];   // 33.8 KB

    int tid = threadIdx.x;
    int wid = tid >> 5, lane = tid & 31;
    int g = lane >> 2, tg = lane & 3;
    int wrow = (wid >> 2) * 32;           // 0 or 32
    int wcol = (wid & 3) * 16;            // 0,16,32,48

    // Preload W fragments (register-resident): Bf[ntile][kstep][hi]
    // b0 slot = logical k (2*tg),  b1 slot = logical k (2*tg+1),  n = col
    uint32_t Bf[2][16][2];
    #pragma unroll
    for (int t = 0; t < 2; t++) {
        int ncol = wcol + t * 8 + g;
        #pragma unroll
        for (int s = 0; s < 16; s++) {
            Bf[t][s][0] = cvt_tf32(__ldg(&W[(s * 8 + 2 * tg)     * 64 + ncol]));
            Bf[t][s][1] = cvt_tf32(__ldg(&W[(s * 8 + 2 * tg + 1) * 64 + ncol]));
        }
    }
    // Bias for this thread's output columns (c0/c2 col, c1/c3 col) per ntile
    float bs0[2], bs1[2];
    #pragma unroll
    for (int t = 0; t < 2; t++) {
        bs0[t] = __ldg(&bias[wcol + t * 8 + 2 * tg]);
        bs1[t] = __ldg(&bias[wcol + t * 8 + 2 * tg + 1]);
    }

    int ntiles = (n + 63) >> 6;
    for (int tile = blockIdx.x; tile < ntiles; tile += gridDim.x) {
        __syncthreads();   // protect As from previous iteration's readers
        // Stage A: 64 rows x 32 float4 of tf32(concat(hin, agg))
        #pragma unroll
        for (int r = 0; r < 8; r++) {
            int idx = tid + 256 * r;
            int row = idx >> 5, q = idx & 31;
            int node = tile * 64 + row;
            float4 v = make_float4(0.f, 0.f, 0.f, 0.f);
            if (node < n)
                v = (q < 16) ? __ldg(&hin4[(size_t)node * 16 + q])
                             : __ldg(&agg4[(size_t)node * 16 + q - 16]);
            uint32_t c0 = cvt_tf32(v.x), c1 = cvt_tf32(v.y);
            uint32_t c2 = cvt_tf32(v.z), c3 = cvt_tf32(v.w);
            uint4* p = reinterpret_cast<uint4*>(&As[row * A_STRIDE + q * 4]);
            *p = make_uint4(c0, c1, c2, c3);
        }
        __syncthreads();

        // Accumulators [mtile][ntile], init with bias
        float c0[2][2], c1[2][2], c2[2][2], c3[2][2];
        #pragma unroll
        for (int m = 0; m < 2; m++)
            #pragma unroll
            for (int t = 0; t < 2; t++) {
                c0[m][t] = bs0[t]; c1[m][t] = bs1[t];
                c2[m][t] = bs0[t]; c3[m][t] = bs1[t];
            }

        #pragma unroll
        for (int s = 0; s < 16; s++) {
            int col = s * 8 + 2 * tg;
            #pragma unroll
            for (int m = 0; m < 2; m++) {
                int r0 = wrow + m * 16 + g;
                uint2 lo = *reinterpret_cast<const uint2*>(&As[r0 * A_STRIDE + col]);
                uint2 hi = *reinterpret_cast<const uint2*>(&As[(r0 + 8) * A_STRIDE + col]);
                // a0 = (row g,   hw k=tg)   = logical 2tg   = lo.x
                // a2 = (row g,   hw k=tg+4) = logical 2tg+1 = lo.y
                // a1 = (row g+8, hw k=tg)                   = hi.x
                // a3 = (row g+8, hw k=tg+4)                 = hi.y
                #pragma unroll
                for (int t = 0; t < 2; t++)
                    mma_tf32(c0[m][t], c1[m][t], c2[m][t], c3[m][t],
                             lo.x, hi.x, lo.y, hi.y, Bf[t][s][0], Bf[t][s][1]);
            }
        }

        // Epilogue: write float2 pairs
        #pragma unroll
        for (int m = 0; m < 2; m++) {
            int row0 = tile * 64 + wrow + m * 16 + g;
            #pragma unroll
            for (int t = 0; t < 2; t++) {
                int col = wcol + t * 8 + 2 * tg;
                float2 lo = make_float2(c0[m][t], c1[m][t]);
                float2 hi = make_float2(c2[m][t], c3[m][t]);
                if (RELU) {
                    lo.x = fmaxf(lo.x, 0.f); lo.y = fmaxf(lo.y, 0.f);
                    hi.x = fmaxf(hi.x, 0.f); hi.y = fmaxf(hi.y, 0.f);
                }
                if (row0 < n)
                    *reinterpret_cast<float2*>(&out[(size_t)row0 * 64 + col]) = lo;
                if (row0 + 8 < n)
                    *reinterpret_cast<float2*>(&out[(size_t)(row0 + 8) * 64 + col]) = hi;
            }
        }
    }
}

// ---------------------------------------------------------------------------
extern "C" void kernel_launch(void* const* d_in, const int* in_sizes, int n_in,
                              void* d_out, int out_size) {
    const float* x  = (const float*)d_in[0];          // [N, 64]
    const int*   ei = (const int*)d_in[1];            // [2, E]
    const float* W0 = (const float*)d_in[2];          // [128, 64]
    const float* b0 = (const float*)d_in[3];          // [64]
    const float* W1 = (const float*)d_in[4];          // [128, 64]
    const float* b1 = (const float*)d_in[5];          // [64]
    float*       out = (float*)d_out;                 // [N, 64]

    int n = in_sizes[0] / D;
    int e = in_sizes[1] / 2;
    const int* src = ei;
    const int* dst = ei + e;

    float* hbuf;
    float* aggbuf;
    cudaGetSymbolAddress((void**)&hbuf, g_h);
    cudaGetSymbolAddress((void**)&aggbuf, g_agg);

    // --- CSR build ---
    zero_deg<<<(n + 255) / 256, 256>>>(n);
    deg_kernel<<<((e + 7) / 8 + 255) / 256, 256>>>(dst, e);
    int nb = (n + 2047) / 2048;
    scan_sum<<<nb, 256>>>(n);
    scan_blocks<<<1, 64>>>(nb, n, e);
    scan_apply<<<nb, 256>>>(n);
    fill_kernel<<<((e + 3) / 4 + 255) / 256, 256>>>(src, dst, e);

    int ntiles = (n + 63) / 64;
    int grid = ntiles < 888 ? ntiles : 888;   // 6 blocks/SM by smem

    // --- Layer 0 ---
    agg_kernel<<<(n + 7) / 8, 256>>>((const float2*)x, n);
    linear_mma<true><<<grid, 256>>>(
        (const float4*)x, (const float4*)aggbuf, W0, b0, hbuf, n);

    // --- Layer 1 ---
    agg_kernel<<<(n + 7) / 8, 256>>>((const float2*)hbuf, n);
    linear_mma<false><<<grid, 256>>>(
        (const float4*)hbuf, (const float4*)aggbuf, W1, b1, out, n);
}